// round 2
// baseline (speedup 1.0000x reference)
#include <cuda_runtime.h>
#include <cuda_fp16.h>
#include <cstdint>

#define B_ 256
#define N_ 192
#define D_ 512
#define E_ 1024
#define H_ 512
#define K_ 58
#define M_ (B_*K_)   // 14848

// ---------------- scratch (static device globals; no allocation) -------------
__device__ __half g_X[(size_t)M_*1024];     // [M,1024] fp16: cols 0:512 = base, 512:1024 = bn(relu(h))
__device__ float  g_hpre[(size_t)M_*H_];    // [M,512] fp32 pre-BN hidden
__device__ float  g_feats[(size_t)M_*E_];   // [M,1024] fp32 feats
__device__ __half g_W1h[H_*D_];             // fp16 W1
__device__ __half g_Wcat[E_*1024];          // fp16 [W_fc | W2]
__device__ float  g_bias2[E_];              // b_fc + b2
__device__ float  g_stats[2*H_];            // col sums / sumsq
__device__ int    g_idx[B_*K_];             // selected patch indices

// ---------------- prep: weight casts + stat zeroing --------------------------
__global__ void prep_kernel(const float* __restrict__ Wfc, const float* __restrict__ bfc,
                            const float* __restrict__ W1,  const float* __restrict__ W2,
                            const float* __restrict__ b2)
{
    int i = blockIdx.x*blockDim.x + threadIdx.x;   // 0..1048575
    {
        int e = i >> 10, c = i & 1023;
        float v = (c < 512) ? Wfc[e*512 + c] : W2[e*512 + (c - 512)];
        g_Wcat[i] = __float2half_rn(v);
    }
    if (i < H_*D_) g_W1h[i] = __float2half_rn(W1[i]);
    if (i < E_)    g_bias2[i] = bfc[i] + b2[i];
    if (i < 2*H_)  g_stats[i] = 0.f;
}

// ---------------- top-K by rank counting (exact lax.top_k set semantics) -----
__global__ void topk_kernel(const float* __restrict__ am)
{
    __shared__ float sv[N_];
    __shared__ int cnt;
    int b = blockIdx.x, t = threadIdx.x;
    if (t == 0) cnt = 0;
    sv[t] = am[(size_t)b*((N_+1)*(N_+1)) + 1 + t];   // attention_map[b,0,1+t]
    __syncthreads();
    float my = sv[t];
    int r = 0;
    #pragma unroll 8
    for (int i = 0; i < N_; ++i) {
        float v = sv[i];
        r += (v > my) || (v == my && i < t);     // tie-break: lower index wins
    }
    if (r < K_) {
        int p = atomicAdd(&cnt, 1);
        g_idx[b*K_ + p] = t;
    }
}

// ---------------- gather + L2 normalize + fp16 --------------------------------
__global__ void gather_kernel(const float* __restrict__ emb)
{
    int row = blockIdx.x;                 // 0..M-1
    int b   = row / K_;
    int p   = g_idx[row];
    const float4* src = (const float4*)(emb + (size_t)(b*N_ + p)*D_);
    int t = threadIdx.x;                  // 128 threads * 4 floats
    float4 v = src[t];
    float s = v.x*v.x + v.y*v.y + v.z*v.z + v.w*v.w;
    #pragma unroll
    for (int o = 16; o; o >>= 1) s += __shfl_xor_sync(0xffffffffu, s, o);
    __shared__ float sm[4];
    if ((t & 31) == 0) sm[t >> 5] = s;
    __syncthreads();
    float nrm = sqrtf(sm[0] + sm[1] + sm[2] + sm[3]) + 1e-8f;
    __half2* dst = (__half2*)(g_X + (size_t)row*1024 + t*4);
    dst[0] = __floats2half2_rn(v.x/nrm, v.y/nrm);
    dst[1] = __floats2half2_rn(v.z/nrm, v.w/nrm);
}

// ---------------- fp16 tensor-core GEMM: C = A @ B^T + bias -------------------
// A: [M,Kdim] fp16 row stride lda; B: [N,Kdim] fp16 row stride ldb; C fp32 ldc.
// BM=128 BN=128 BK=32, 256 threads (8 warps, 2x4 warp grid, 64x32 per warp),
// cp.async 2-stage pipeline, XOR-swizzled smem, ldmatrix fragments.
#define BM 128
#define BN 128
#define BK 32

__device__ __forceinline__ int swz(int r, int kc) {   // half-element offset
    return r*32 + (((kc ^ (r >> 1)) & 3) << 3);
}
__device__ __forceinline__ void cp16(uint32_t dst, const void* src) {
    asm volatile("cp.async.cg.shared.global [%0], [%1], 16;\n" :: "r"(dst), "l"(src));
}

__global__ __launch_bounds__(256, 2)
void gemm_kernel(const __half* __restrict__ A, int lda,
                 const __half* __restrict__ Bm, int ldb,
                 float* __restrict__ C, int ldc,
                 const float* __restrict__ bias, int Kdim)
{
    __shared__ __half sh[2][2][BM*BK];   // [stage][A/B][128*32]
    const int tid  = threadIdx.x;
    const int lane = tid & 31, wid = tid >> 5;
    const int wm = wid >> 2, wn = wid & 3;
    const int m0 = blockIdx.y*BM, n0 = blockIdx.x*BN;

    uint32_t sbase = (uint32_t)__cvta_generic_to_shared(&sh[0][0][0]);

    float acc[4][4][4];
    #pragma unroll
    for (int i = 0; i < 4; ++i)
        #pragma unroll
        for (int j = 0; j < 4; ++j)
            #pragma unroll
            for (int k = 0; k < 4; ++k) acc[i][j][k] = 0.f;

    // global->smem copy descriptors (each thread: 2 A chunks + 2 B chunks)
    const int lr = tid >> 2;          // 0..63
    const int lc = tid & 3;           // 16B chunk 0..3
    const __half* Ag0 = A  + (size_t)(m0 + lr     )*lda + lc*8;
    const __half* Ag1 = A  + (size_t)(m0 + lr + 64)*lda + lc*8;
    const __half* Bg0 = Bm + (size_t)(n0 + lr     )*ldb + lc*8;
    const __half* Bg1 = Bm + (size_t)(n0 + lr + 64)*ldb + lc*8;
    const uint32_t sA0 = sbase        + swz(lr,      lc)*2;
    const uint32_t sA1 = sbase        + swz(lr + 64, lc)*2;
    const uint32_t sB0 = sbase + 8192 + swz(lr,      lc)*2;
    const uint32_t sB1 = sbase + 8192 + swz(lr + 64, lc)*2;

    // ldmatrix per-lane row descriptors
    const int mi  = lane >> 3;        // matrix index within x4
    const int lr8 = lane & 7;
    int arow[4];
    #pragma unroll
    for (int mt = 0; mt < 4; ++mt) arow[mt] = wm*64 + mt*16 + ((mi & 1) << 3) + lr8;
    const int akadd = mi >> 1;
    int brow[2];
    #pragma unroll
    for (int p = 0; p < 2; ++p) brow[p] = wn*32 + ((2*p + (mi >> 1)) << 3) + lr8;
    const int bkadd = mi & 1;

    auto issue = [&](int kt, int st) {
        uint32_t so = st*16384;
        int ko = kt*BK;
        cp16(sA0 + so, Ag0 + ko);  cp16(sA1 + so, Ag1 + ko);
        cp16(sB0 + so, Bg0 + ko);  cp16(sB1 + so, Bg1 + ko);
        asm volatile("cp.async.commit_group;\n");
    };

    auto compute = [&](int st) {
        uint32_t abase = sbase + st*16384;
        uint32_t bbase = abase + 8192;
        #pragma unroll
        for (int ks = 0; ks < 2; ++ks) {
            uint32_t a[4][4], bb[4][2];
            #pragma unroll
            for (int mt = 0; mt < 4; ++mt) {
                uint32_t ad = abase + swz(arow[mt], 2*ks + akadd)*2;
                asm volatile("ldmatrix.sync.aligned.m8n8.x4.shared.b16 {%0,%1,%2,%3},[%4];"
                    : "=r"(a[mt][0]), "=r"(a[mt][1]), "=r"(a[mt][2]), "=r"(a[mt][3]) : "r"(ad));
            }
            // B stored [n][k]: mma row.col wants k-pairs per fixed n -> NON-trans ldmatrix.
            #pragma unroll
            for (int p = 0; p < 2; ++p) {
                uint32_t bd = bbase + swz(brow[p], 2*ks + bkadd)*2;
                asm volatile("ldmatrix.sync.aligned.m8n8.x4.shared.b16 {%0,%1,%2,%3},[%4];"
                    : "=r"(bb[2*p][0]), "=r"(bb[2*p][1]),
                      "=r"(bb[2*p+1][0]), "=r"(bb[2*p+1][1]) : "r"(bd));
            }
            #pragma unroll
            for (int mt = 0; mt < 4; ++mt)
                #pragma unroll
                for (int nt = 0; nt < 4; ++nt)
                    asm volatile(
                        "mma.sync.aligned.m16n8k16.row.col.f32.f16.f16.f32 "
                        "{%0,%1,%2,%3},{%4,%5,%6,%7},{%8,%9},{%0,%1,%2,%3};\n"
                        : "+f"(acc[mt][nt][0]), "+f"(acc[mt][nt][1]),
                          "+f"(acc[mt][nt][2]), "+f"(acc[mt][nt][3])
                        : "r"(a[mt][0]), "r"(a[mt][1]), "r"(a[mt][2]), "r"(a[mt][3]),
                          "r"(bb[nt][0]), "r"(bb[nt][1]));
        }
    };

    const int ntile = Kdim / BK;
    issue(0, 0);
    for (int t = 0; t < ntile; ++t) {
        if (t + 1 < ntile) issue(t + 1, (t + 1) & 1);
        if (t + 1 < ntile) asm volatile("cp.async.wait_group 1;\n");
        else               asm volatile("cp.async.wait_group 0;\n");
        __syncthreads();
        compute(t & 1);
        __syncthreads();
    }

    // epilogue: + bias, fp32 out
    const int g = lane >> 2, q = lane & 3;
    #pragma unroll
    for (int mt = 0; mt < 4; ++mt) {
        #pragma unroll
        for (int nt = 0; nt < 4; ++nt) {
            int r = m0 + wm*64 + mt*16 + g;
            int c = n0 + wn*32 + nt*8 + q*2;
            float b0 = bias[c], b1 = bias[c+1];
            float2 v0 = make_float2(acc[mt][nt][0] + b0, acc[mt][nt][1] + b1);
            float2 v1 = make_float2(acc[mt][nt][2] + b0, acc[mt][nt][3] + b1);
            *(float2*)&C[(size_t)r*ldc + c]       = v0;
            *(float2*)&C[(size_t)(r + 8)*ldc + c] = v1;
        }
    }
}

// ---------------- BN column stats over M rows ---------------------------------
__global__ void bnstats_kernel()
{
    int c  = blockIdx.x*128 + threadIdx.x;   // grid.x=4
    int r0 = blockIdx.y*256;                 // grid.y=58
    float s = 0.f, ss = 0.f;
    for (int r = r0; r < r0 + 256; ++r) {
        float v = g_hpre[(size_t)r*H_ + c];
        s += v; ss += v*v;
    }
    atomicAdd(&g_stats[c], s);
    atomicAdd(&g_stats[H_ + c], ss);
}

// ---------------- BN apply + ReLU + fp16 into X[:,512:] -----------------------
__global__ void bnapply_kernel(const float* __restrict__ gamma, const float* __restrict__ beta)
{
    int i = blockIdx.x*256 + threadIdx.x;    // 0..M*H-1
    int c = i & (H_ - 1);
    float x = g_hpre[i];
    const float invM = 1.f / (float)M_;
    float mu  = g_stats[c] * invM;
    float var = g_stats[H_ + c] * invM - mu*mu;
    float y = (x - mu) * rsqrtf(var + 1e-5f) * gamma[c] + beta[c];
    y = fmaxf(y, 0.f);
    int r = i >> 9;
    g_X[(size_t)r*1024 + 512 + c] = __float2half_rn(y);
}

// ---------------- max over K per batch ----------------------------------------
__global__ void maxreduce_kernel(float* __restrict__ out)
{
    int b = blockIdx.x;
    int e = blockIdx.y*256 + threadIdx.x;
    const float* f = g_feats + (size_t)b*K_*E_ + e;
    float m = f[0];
    #pragma unroll 8
    for (int k = 1; k < K_; ++k) m = fmaxf(m, f[(size_t)k*E_]);
    out[(size_t)b*E_ + e] = m;
}

// ---------------- launch ------------------------------------------------------
extern "C" void kernel_launch(void* const* d_in, const int* in_sizes, int n_in,
                              void* d_out, int out_size)
{
    const float* emb   = (const float*)d_in[0];
    const float* am    = (const float*)d_in[1];
    const float* Wfc   = (const float*)d_in[2];
    const float* bfc   = (const float*)d_in[3];
    const float* W1    = (const float*)d_in[4];
    const float* b1    = (const float*)d_in[5];
    const float* gamma = (const float*)d_in[6];
    const float* beta  = (const float*)d_in[7];
    const float* W2    = (const float*)d_in[8];
    const float* b2    = (const float*)d_in[9];
    float* out = (float*)d_out;

    void *pX, *pW1h, *pWcat, *pH, *pF, *pB2;
    cudaGetSymbolAddress(&pX,    g_X);
    cudaGetSymbolAddress(&pW1h,  g_W1h);
    cudaGetSymbolAddress(&pWcat, g_Wcat);
    cudaGetSymbolAddress(&pH,    g_hpre);
    cudaGetSymbolAddress(&pF,    g_feats);
    cudaGetSymbolAddress(&pB2,   g_bias2);

    prep_kernel<<<4096, 256>>>(Wfc, bfc, W1, W2, b2);
    topk_kernel<<<B_, N_>>>(am);
    gather_kernel<<<M_, 128>>>(emb);
    // h_pre = base @ W1^T + b1   (M x 512, K=512; A = X cols 0:512 via lda=1024)
    gemm_kernel<<<dim3(H_/BN, M_/BM), 256>>>((const __half*)pX, 1024,
                                             (const __half*)pW1h, D_,
                                             (float*)pH, H_, b1, D_);
    bnstats_kernel<<<dim3(4, 58), 128>>>();
    bnapply_kernel<<<(M_*H_)/256, 256>>>(gamma, beta);
    // feats = X @ [Wfc|W2]^T + (b_fc+b2)   (M x 1024, K=1024)
    gemm_kernel<<<dim3(E_/BN, M_/BM), 256>>>((const __half*)pX, 1024,
                                             (const __half*)pWcat, 1024,
                                             (float*)pF, E_, (const float*)pB2, 1024);
    maxreduce_kernel<<<dim3(B_, 4), 256>>>(out);
}

// round 3
// speedup vs baseline: 1.0483x; 1.0483x over previous
#include <cuda_runtime.h>
#include <cuda_fp16.h>
#include <cstdint>

#define B_ 256
#define N_ 192
#define D_ 512
#define E_ 1024
#define H_ 512
#define K_ 58
#define M_ (B_*K_)        // 14848 real rows
#define MP_ (B_*64)       // 16384 padded rows (64 per batch, rows k>=58 stay zero)

// ---------------- scratch (static device globals; zero-init, no allocation) --
__device__ __half g_X[(size_t)MP_*1024];    // [MP,1024] fp16: 0:512 base, 512:1024 bn(relu(h)); padding rows = 0
__device__ float  g_hpre[(size_t)MP_*H_];   // [MP,512] fp32 pre-BN hidden
__device__ __half g_W1h[H_*D_];             // fp16 W1
__device__ __half g_Wcat[E_*1024];          // fp16 [W_fc | W2]
__device__ float  g_bias2[E_];              // b_fc + b2
__device__ float  g_stats[2*H_];            // col sums / sumsq (fused from GEMM1)
__device__ int    g_idx[B_*K_];             // selected patch indices

// ---------------- prep: weight casts + stat zeroing --------------------------
__global__ void prep_kernel(const float* __restrict__ Wfc, const float* __restrict__ bfc,
                            const float* __restrict__ W1,  const float* __restrict__ W2,
                            const float* __restrict__ b2)
{
    int i = blockIdx.x*blockDim.x + threadIdx.x;   // 0..1048575
    {
        int e = i >> 10, c = i & 1023;
        float v = (c < 512) ? Wfc[e*512 + c] : W2[e*512 + (c - 512)];
        g_Wcat[i] = __float2half_rn(v);
    }
    if (i < H_*D_) g_W1h[i] = __float2half_rn(W1[i]);
    if (i < E_)    g_bias2[i] = bfc[i] + b2[i];
    if (i < 2*H_)  g_stats[i] = 0.f;
}

// ---------------- top-K by rank counting (exact lax.top_k set semantics) -----
__global__ void topk_kernel(const float* __restrict__ am)
{
    __shared__ float sv[N_];
    __shared__ int cnt;
    int b = blockIdx.x, t = threadIdx.x;
    if (t == 0) cnt = 0;
    sv[t] = am[(size_t)b*((N_+1)*(N_+1)) + 1 + t];
    __syncthreads();
    float my = sv[t];
    int r = 0;
    #pragma unroll 8
    for (int i = 0; i < N_; ++i) {
        float v = sv[i];
        r += (v > my) || (v == my && i < t);
    }
    if (r < K_) {
        int p = atomicAdd(&cnt, 1);
        g_idx[b*K_ + p] = t;
    }
}

// ---------------- gather + L2 normalize + fp16 (into padded layout) -----------
__global__ void gather_kernel(const float* __restrict__ emb)
{
    int row = blockIdx.x;                 // 0..M_-1
    int b   = row / K_;
    int k   = row - b*K_;
    int p   = g_idx[row];
    const float4* src = (const float4*)(emb + (size_t)(b*N_ + p)*D_);
    int t = threadIdx.x;
    float4 v = src[t];
    float s = v.x*v.x + v.y*v.y + v.z*v.z + v.w*v.w;
    #pragma unroll
    for (int o = 16; o; o >>= 1) s += __shfl_xor_sync(0xffffffffu, s, o);
    __shared__ float sm[4];
    if ((t & 31) == 0) sm[t >> 5] = s;
    __syncthreads();
    float nrm = sqrtf(sm[0] + sm[1] + sm[2] + sm[3]) + 1e-8f;
    size_t r = (size_t)(b*64 + k);
    __half2* dst = (__half2*)(g_X + r*1024 + t*4);
    dst[0] = __floats2half2_rn(v.x/nrm, v.y/nrm);
    dst[1] = __floats2half2_rn(v.z/nrm, v.w/nrm);
}

// ---------------- fp16 tensor-core GEMM: C = A @ B^T + bias -------------------
// 3-stage cp.async pipeline, XOR-swizzled smem, ldmatrix, m16n8k16 mma.
// BMt=128 (FSTAT): also accumulates BN column sums/sumsq (masked to real rows).
// BMt=64  (FMAX) : one batch per CTA; epilogue computes max over K, writes out.
#define BN 128
#define BK 32

__device__ __forceinline__ int swz(int r, int kc) {   // half-element offset
    return r*32 + (((kc ^ (r >> 1)) & 3) << 3);
}
__device__ __forceinline__ void cp16(uint32_t dst, const void* src) {
    asm volatile("cp.async.cg.shared.global [%0], [%1], 16;\n" :: "r"(dst), "l"(src));
}

template<int BMt, bool FSTAT, bool FMAX>
__global__ __launch_bounds__(256)
void gemm_tc(const __half* __restrict__ A, int lda,
             const __half* __restrict__ Bm, int ldb,
             float* __restrict__ C, int ldc,
             const float* __restrict__ bias, int Kdim,
             float* __restrict__ stats, float* __restrict__ omax)
{
    constexpr int MT  = BMt/32;          // m16 tiles per warp (2 warp-rows)
    constexpr int STG = 3;
    constexpr int STAGE_HALFS = (BMt + BN)*BK;
    __shared__ __half sh[STG*STAGE_HALFS];

    const int tid  = threadIdx.x;
    const int lane = tid & 31, wid = tid >> 5;
    const int wm = wid >> 2, wn = wid & 3;
    const int m0 = blockIdx.y*BMt, n0 = blockIdx.x*BN;

    uint32_t sbase = (uint32_t)__cvta_generic_to_shared(&sh[0]);

    float acc[MT][4][4];
    #pragma unroll
    for (int i = 0; i < MT; ++i)
        #pragma unroll
        for (int j = 0; j < 4; ++j)
            #pragma unroll
            for (int k = 0; k < 4; ++k) acc[i][j][k] = 0.f;

    // global->smem descriptors
    const int lr = tid >> 2;          // 0..63
    const int lc = tid & 3;           // 16B chunk
    const __half* Ag0 = A  + (size_t)(m0 + lr)*lda + lc*8;
    const __half* Bg0 = Bm + (size_t)(n0 + lr)*ldb + lc*8;
    const __half* Bg1 = Bm + (size_t)(n0 + lr + 64)*ldb + lc*8;
    const uint32_t oA0 = swz(lr, lc)*2;
    const uint32_t oB0 = BMt*BK*2 + swz(lr, lc)*2;
    const uint32_t oB1 = BMt*BK*2 + swz(lr + 64, lc)*2;
    const __half* Ag1 = (BMt == 128) ? A + (size_t)(m0 + lr + 64)*lda + lc*8 : Ag0;
    const uint32_t oA1 = (BMt == 128) ? swz(lr + 64, lc)*2 : oA0;

    // ldmatrix per-lane descriptors
    const int mi  = lane >> 3;
    const int lr8 = lane & 7;
    int arow[MT];
    #pragma unroll
    for (int mt = 0; mt < MT; ++mt) arow[mt] = wm*(BMt/2) + mt*16 + ((mi & 1) << 3) + lr8;
    const int akadd = mi >> 1;
    int brow[2];
    #pragma unroll
    for (int p = 0; p < 2; ++p) brow[p] = wn*32 + ((2*p + (mi >> 1)) << 3) + lr8;
    const int bkadd = mi & 1;

    auto issue = [&](int kt, int st) {
        uint32_t so = st*STAGE_HALFS*2;
        int ko = kt*BK;
        cp16(sbase + so + oA0, Ag0 + ko);
        if (BMt == 128) cp16(sbase + so + oA1, Ag1 + ko);
        cp16(sbase + so + oB0, Bg0 + ko);
        cp16(sbase + so + oB1, Bg1 + ko);
        asm volatile("cp.async.commit_group;\n");
    };

    auto compute = [&](int st) {
        uint32_t abase = sbase + st*STAGE_HALFS*2;
        uint32_t bbase = abase + BMt*BK*2;
        #pragma unroll
        for (int ks = 0; ks < 2; ++ks) {
            uint32_t a[MT][4], bb[4][2];
            #pragma unroll
            for (int mt = 0; mt < MT; ++mt) {
                uint32_t ad = abase + swz(arow[mt], 2*ks + akadd)*2;
                asm volatile("ldmatrix.sync.aligned.m8n8.x4.shared.b16 {%0,%1,%2,%3},[%4];"
                    : "=r"(a[mt][0]), "=r"(a[mt][1]), "=r"(a[mt][2]), "=r"(a[mt][3]) : "r"(ad));
            }
            #pragma unroll
            for (int p = 0; p < 2; ++p) {
                uint32_t bd = bbase + swz(brow[p], 2*ks + bkadd)*2;
                asm volatile("ldmatrix.sync.aligned.m8n8.x4.shared.b16 {%0,%1,%2,%3},[%4];"
                    : "=r"(bb[2*p][0]), "=r"(bb[2*p][1]),
                      "=r"(bb[2*p+1][0]), "=r"(bb[2*p+1][1]) : "r"(bd));
            }
            #pragma unroll
            for (int mt = 0; mt < MT; ++mt)
                #pragma unroll
                for (int nt = 0; nt < 4; ++nt)
                    asm volatile(
                        "mma.sync.aligned.m16n8k16.row.col.f32.f16.f16.f32 "
                        "{%0,%1,%2,%3},{%4,%5,%6,%7},{%8,%9},{%0,%1,%2,%3};\n"
                        : "+f"(acc[mt][nt][0]), "+f"(acc[mt][nt][1]),
                          "+f"(acc[mt][nt][2]), "+f"(acc[mt][nt][3])
                        : "r"(a[mt][0]), "r"(a[mt][1]), "r"(a[mt][2]), "r"(a[mt][3]),
                          "r"(bb[nt][0]), "r"(bb[nt][1]));
        }
    };

    const int ntile = Kdim / BK;
    issue(0, 0);
    issue(1, 1);
    for (int t = 0; t < ntile; ++t) {
        if (t + 1 < ntile) asm volatile("cp.async.wait_group 1;\n");
        else               asm volatile("cp.async.wait_group 0;\n");
        __syncthreads();
        compute(t % STG);
        if (t + 2 < ntile) issue(t + 2, (t + 2) % STG);
    }

    const int g = lane >> 2, q = lane & 3;

    if (FSTAT) {
        // C store (hpre, all rows incl. padding) + masked BN stat accumulation.
        float sum[8], sq[8];
        #pragma unroll
        for (int i = 0; i < 8; ++i) { sum[i] = 0.f; sq[i] = 0.f; }
        #pragma unroll
        for (int mt = 0; mt < MT; ++mt) {
            int rr = wm*(BMt/2) + mt*16 + g;            // row-in-tile (r and r+8 same batch)
            bool ok0 = (rr & 63) < K_;
            bool ok1 = ((rr + 8) & 63) < K_;
            #pragma unroll
            for (int nt = 0; nt < 4; ++nt) {
                int c = n0 + wn*32 + nt*8 + q*2;
                float b0 = bias[c], b1 = bias[c+1];
                float v00 = acc[mt][nt][0] + b0, v01 = acc[mt][nt][1] + b1;
                float v10 = acc[mt][nt][2] + b0, v11 = acc[mt][nt][3] + b1;
                int r = m0 + rr;
                *(float2*)&C[(size_t)r*ldc + c]     = make_float2(v00, v01);
                *(float2*)&C[(size_t)(r+8)*ldc + c] = make_float2(v10, v11);
                if (ok0) { sum[nt*2]   += v00; sq[nt*2]   += v00*v00;
                           sum[nt*2+1] += v01; sq[nt*2+1] += v01*v01; }
                if (ok1) { sum[nt*2]   += v10; sq[nt*2]   += v10*v10;
                           sum[nt*2+1] += v11; sq[nt*2+1] += v11*v11; }
            }
        }
        #pragma unroll
        for (int off = 4; off < 32; off <<= 1) {
            #pragma unroll
            for (int i = 0; i < 8; ++i) {
                sum[i] += __shfl_xor_sync(0xffffffffu, sum[i], off);
                sq[i]  += __shfl_xor_sync(0xffffffffu, sq[i],  off);
            }
        }
        if (lane < 4) {
            #pragma unroll
            for (int nt = 0; nt < 4; ++nt) {
                #pragma unroll
                for (int j = 0; j < 2; ++j) {
                    int c = n0 + wn*32 + nt*8 + lane*2 + j;
                    atomicAdd(&stats[c],      sum[nt*2+j]);
                    atomicAdd(&stats[H_ + c], sq[nt*2+j]);
                }
            }
        }
    } else if (FMAX) {
        // One batch per CTA: masked max over K, no C store.
        float mx[8];
        #pragma unroll
        for (int i = 0; i < 8; ++i) mx[i] = -3.4e38f;
        #pragma unroll
        for (int mt = 0; mt < MT; ++mt) {
            int k0 = wm*(BMt/2) + mt*16 + g;
            bool ok0 = k0 < K_, ok1 = (k0 + 8) < K_;
            #pragma unroll
            for (int nt = 0; nt < 4; ++nt) {
                int c = n0 + wn*32 + nt*8 + q*2;
                float b0 = bias[c], b1 = bias[c+1];
                if (ok0) { mx[nt*2]   = fmaxf(mx[nt*2],   acc[mt][nt][0] + b0);
                           mx[nt*2+1] = fmaxf(mx[nt*2+1], acc[mt][nt][1] + b1); }
                if (ok1) { mx[nt*2]   = fmaxf(mx[nt*2],   acc[mt][nt][2] + b0);
                           mx[nt*2+1] = fmaxf(mx[nt*2+1], acc[mt][nt][3] + b1); }
            }
        }
        #pragma unroll
        for (int off = 4; off < 32; off <<= 1)
            #pragma unroll
            for (int i = 0; i < 8; ++i)
                mx[i] = fmaxf(mx[i], __shfl_xor_sync(0xffffffffu, mx[i], off));
        __syncthreads();                       // smem reuse after mainloop
        float* buf = (float*)sh;               // [2][BN]
        if (lane < 4) {
            #pragma unroll
            for (int nt = 0; nt < 4; ++nt)
                #pragma unroll
                for (int j = 0; j < 2; ++j)
                    buf[wm*BN + wn*32 + nt*8 + lane*2 + j] = mx[nt*2+j];
        }
        __syncthreads();
        if (tid < BN) {
            int b = blockIdx.y;
            omax[(size_t)b*E_ + n0 + tid] = fmaxf(buf[tid], buf[BN + tid]);
        }
    }
}

// ---------------- BN apply + ReLU + fp16 into X[:,512:] (real rows only) ------
__global__ void bnapply_kernel(const float* __restrict__ gamma, const float* __restrict__ beta)
{
    int i = blockIdx.x*256 + threadIdx.x;    // 0..M_*H_-1
    int row = i >> 9;                        // real row 0..14847
    int c = i & (H_ - 1);
    int b = row / K_;
    int k = row - b*K_;
    size_t r = (size_t)(b*64 + k);
    float x = g_hpre[r*H_ + c];
    const float invM = 1.f / (float)M_;
    float mu  = g_stats[c] * invM;
    float var = g_stats[H_ + c] * invM - mu*mu;
    float y = (x - mu) * rsqrtf(var + 1e-5f) * gamma[c] + beta[c];
    y = fmaxf(y, 0.f);
    g_X[r*1024 + 512 + c] = __float2half_rn(y);
}

// ---------------- launch ------------------------------------------------------
extern "C" void kernel_launch(void* const* d_in, const int* in_sizes, int n_in,
                              void* d_out, int out_size)
{
    const float* emb   = (const float*)d_in[0];
    const float* am    = (const float*)d_in[1];
    const float* Wfc   = (const float*)d_in[2];
    const float* bfc   = (const float*)d_in[3];
    const float* W1    = (const float*)d_in[4];
    const float* b1    = (const float*)d_in[5];
    const float* gamma = (const float*)d_in[6];
    const float* beta  = (const float*)d_in[7];
    const float* W2    = (const float*)d_in[8];
    const float* b2    = (const float*)d_in[9];
    float* out = (float*)d_out;

    void *pX, *pW1h, *pWcat, *pH, *pB2, *pSt;
    cudaGetSymbolAddress(&pX,    g_X);
    cudaGetSymbolAddress(&pW1h,  g_W1h);
    cudaGetSymbolAddress(&pWcat, g_Wcat);
    cudaGetSymbolAddress(&pH,    g_hpre);
    cudaGetSymbolAddress(&pB2,   g_bias2);
    cudaGetSymbolAddress(&pSt,   g_stats);

    prep_kernel<<<4096, 256>>>(Wfc, bfc, W1, W2, b2);
    topk_kernel<<<B_, N_>>>(am);
    gather_kernel<<<M_, 128>>>(emb);
    // GEMM1: hpre = base @ W1^T + b1, fused BN stats (masked to real rows)
    gemm_tc<128, true, false><<<dim3(H_/BN, MP_/128), 256>>>(
        (const __half*)pX, 1024, (const __half*)pW1h, D_,
        (float*)pH, H_, b1, D_, (float*)pSt, nullptr);
    bnapply_kernel<<<(M_*H_)/256, 256>>>(gamma, beta);
    // GEMM2: out[b,:] = max_k( X @ [Wfc|W2]^T + (b_fc+b2) ), fused max epilogue
    gemm_tc<64, false, true><<<dim3(E_/BN, MP_/64), 256>>>(
        (const __half*)pX, 1024, (const __half*)pWcat, 1024,
        nullptr, 0, (const float*)pB2, 1024, nullptr, out);
}

// round 4
// speedup vs baseline: 1.1538x; 1.1006x over previous
#include <cuda_runtime.h>
#include <cuda_fp16.h>
#include <cstdint>

#define B_ 256
#define N_ 192
#define D_ 512
#define E_ 1024
#define H_ 512
#define K_ 58
#define M_ (B_*K_)        // 14848 real rows
#define MP_ (B_*64)       // 16384 padded rows (64 per batch, rows k>=58 stay zero)

// ---------------- scratch (static device globals; zero-init, no allocation) --
__device__ __half g_X[(size_t)MP_*1024];    // [MP,1024] fp16: 0:512 base, 512:1024 bn(relu(h)); padding rows = 0
__device__ __half g_hpre[(size_t)MP_*H_];   // [MP,512] fp16 pre-BN hidden
__device__ __half g_W1h[H_*D_];             // fp16 W1
__device__ __half g_Wcat[E_*1024];          // fp16 [W_fc | W2]
__device__ float  g_bias2[E_];              // b_fc + b2
__device__ float  g_stats[2*H_];            // col sums / sumsq (fused from GEMM1, fp32 accs)
__device__ int    g_idx[B_*K_];             // selected patch indices

// ---------------- prep: weight casts + stat zeroing --------------------------
__global__ void prep_kernel(const float* __restrict__ Wfc, const float* __restrict__ bfc,
                            const float* __restrict__ W1,  const float* __restrict__ W2,
                            const float* __restrict__ b2)
{
    int i = blockIdx.x*blockDim.x + threadIdx.x;   // 0..1048575
    {
        int e = i >> 10, c = i & 1023;
        float v = (c < 512) ? Wfc[e*512 + c] : W2[e*512 + (c - 512)];
        g_Wcat[i] = __float2half_rn(v);
    }
    if (i < H_*D_) g_W1h[i] = __float2half_rn(W1[i]);
    if (i < E_)    g_bias2[i] = bfc[i] + b2[i];
    if (i < 2*H_)  g_stats[i] = 0.f;
}

// ---------------- top-K by rank counting (exact lax.top_k set semantics) -----
__global__ void topk_kernel(const float* __restrict__ am)
{
    __shared__ float sv[N_];
    __shared__ int cnt;
    int b = blockIdx.x, t = threadIdx.x;
    if (t == 0) cnt = 0;
    sv[t] = am[(size_t)b*((N_+1)*(N_+1)) + 1 + t];
    __syncthreads();
    float my = sv[t];
    int r = 0;
    #pragma unroll 8
    for (int i = 0; i < N_; ++i) {
        float v = sv[i];
        r += (v > my) || (v == my && i < t);
    }
    if (r < K_) {
        int p = atomicAdd(&cnt, 1);
        g_idx[b*K_ + p] = t;
    }
}

// ---------------- gather + L2 normalize + fp16 (into padded layout) -----------
__global__ void gather_kernel(const float* __restrict__ emb)
{
    int row = blockIdx.x;                 // 0..M_-1
    int b   = row / K_;
    int k   = row - b*K_;
    int p   = g_idx[row];
    const float4* src = (const float4*)(emb + (size_t)(b*N_ + p)*D_);
    int t = threadIdx.x;
    float4 v = src[t];
    float s = v.x*v.x + v.y*v.y + v.z*v.z + v.w*v.w;
    #pragma unroll
    for (int o = 16; o; o >>= 1) s += __shfl_xor_sync(0xffffffffu, s, o);
    __shared__ float sm[4];
    if ((t & 31) == 0) sm[t >> 5] = s;
    __syncthreads();
    float nrm = sqrtf(sm[0] + sm[1] + sm[2] + sm[3]) + 1e-8f;
    size_t r = (size_t)(b*64 + k);
    __half2* dst = (__half2*)(g_X + r*1024 + t*4);
    dst[0] = __floats2half2_rn(v.x/nrm, v.y/nrm);
    dst[1] = __floats2half2_rn(v.z/nrm, v.w/nrm);
}

// ---------------- fp16 tensor-core GEMM: C = A @ B^T + bias -------------------
// 3-stage cp.async pipeline, XOR-swizzled smem, ldmatrix, m16n8k16 mma.
// FSTAT: stores fp16 C and accumulates BN column sums/sumsq (masked rows).
// FMAX : BM=128 = 2 batches; warp-local masked max over K, writes out directly.
#define BMt 128
#define BN 128
#define BK 32

__device__ __forceinline__ int swz(int r, int kc) {   // half-element offset
    return r*32 + (((kc ^ (r >> 1)) & 3) << 3);
}
__device__ __forceinline__ void cp16(uint32_t dst, const void* src) {
    asm volatile("cp.async.cg.shared.global [%0], [%1], 16;\n" :: "r"(dst), "l"(src));
}

template<bool FSTAT>
__global__ __launch_bounds__(256)
void gemm_tc(const __half* __restrict__ A, int lda,
             const __half* __restrict__ Bm, int ldb,
             __half* __restrict__ Ch, int ldc,
             const float* __restrict__ bias, int Kdim,
             float* __restrict__ stats, float* __restrict__ omax)
{
    constexpr int MT  = 4;               // m16 tiles per warp
    constexpr int STG = 3;
    constexpr int STAGE_HALFS = (BMt + BN)*BK;
    __shared__ __half sh[STG*STAGE_HALFS];   // 48 KB

    const int tid  = threadIdx.x;
    const int lane = tid & 31, wid = tid >> 5;
    const int wm = wid >> 2, wn = wid & 3;
    const int m0 = blockIdx.y*BMt, n0 = blockIdx.x*BN;

    uint32_t sbase = (uint32_t)__cvta_generic_to_shared(&sh[0]);

    float acc[MT][4][4];
    #pragma unroll
    for (int i = 0; i < MT; ++i)
        #pragma unroll
        for (int j = 0; j < 4; ++j)
            #pragma unroll
            for (int k = 0; k < 4; ++k) acc[i][j][k] = 0.f;

    // global->smem descriptors
    const int lr = tid >> 2;          // 0..63
    const int lc = tid & 3;           // 16B chunk
    const __half* Ag0 = A  + (size_t)(m0 + lr)*lda + lc*8;
    const __half* Ag1 = A  + (size_t)(m0 + lr + 64)*lda + lc*8;
    const __half* Bg0 = Bm + (size_t)(n0 + lr)*ldb + lc*8;
    const __half* Bg1 = Bm + (size_t)(n0 + lr + 64)*ldb + lc*8;
    const uint32_t oA0 = swz(lr, lc)*2;
    const uint32_t oA1 = swz(lr + 64, lc)*2;
    const uint32_t oB0 = BMt*BK*2 + swz(lr, lc)*2;
    const uint32_t oB1 = BMt*BK*2 + swz(lr + 64, lc)*2;

    // ldmatrix per-lane descriptors
    const int mi  = lane >> 3;
    const int lr8 = lane & 7;
    int arow[MT];
    #pragma unroll
    for (int mt = 0; mt < MT; ++mt) arow[mt] = wm*64 + mt*16 + ((mi & 1) << 3) + lr8;
    const int akadd = mi >> 1;
    int brow[2];
    #pragma unroll
    for (int p = 0; p < 2; ++p) brow[p] = wn*32 + ((2*p + (mi >> 1)) << 3) + lr8;
    const int bkadd = mi & 1;

    auto issue = [&](int kt, int st) {
        uint32_t so = st*STAGE_HALFS*2;
        int ko = kt*BK;
        cp16(sbase + so + oA0, Ag0 + ko);
        cp16(sbase + so + oA1, Ag1 + ko);
        cp16(sbase + so + oB0, Bg0 + ko);
        cp16(sbase + so + oB1, Bg1 + ko);
        asm volatile("cp.async.commit_group;\n");
    };

    auto compute = [&](int st) {
        uint32_t abase = sbase + st*STAGE_HALFS*2;
        uint32_t bbase = abase + BMt*BK*2;
        #pragma unroll
        for (int ks = 0; ks < 2; ++ks) {
            uint32_t a[MT][4], bb[4][2];
            #pragma unroll
            for (int mt = 0; mt < MT; ++mt) {
                uint32_t ad = abase + swz(arow[mt], 2*ks + akadd)*2;
                asm volatile("ldmatrix.sync.aligned.m8n8.x4.shared.b16 {%0,%1,%2,%3},[%4];"
                    : "=r"(a[mt][0]), "=r"(a[mt][1]), "=r"(a[mt][2]), "=r"(a[mt][3]) : "r"(ad));
            }
            #pragma unroll
            for (int p = 0; p < 2; ++p) {
                uint32_t bd = bbase + swz(brow[p], 2*ks + bkadd)*2;
                asm volatile("ldmatrix.sync.aligned.m8n8.x4.shared.b16 {%0,%1,%2,%3},[%4];"
                    : "=r"(bb[2*p][0]), "=r"(bb[2*p][1]),
                      "=r"(bb[2*p+1][0]), "=r"(bb[2*p+1][1]) : "r"(bd));
            }
            #pragma unroll
            for (int mt = 0; mt < MT; ++mt)
                #pragma unroll
                for (int nt = 0; nt < 4; ++nt)
                    asm volatile(
                        "mma.sync.aligned.m16n8k16.row.col.f32.f16.f16.f32 "
                        "{%0,%1,%2,%3},{%4,%5,%6,%7},{%8,%9},{%0,%1,%2,%3};\n"
                        : "+f"(acc[mt][nt][0]), "+f"(acc[mt][nt][1]),
                          "+f"(acc[mt][nt][2]), "+f"(acc[mt][nt][3])
                        : "r"(a[mt][0]), "r"(a[mt][1]), "r"(a[mt][2]), "r"(a[mt][3]),
                          "r"(bb[nt][0]), "r"(bb[nt][1]));
        }
    };

    const int ntile = Kdim / BK;
    issue(0, 0);
    issue(1, 1);
    for (int t = 0; t < ntile; ++t) {
        if (t + 1 < ntile) asm volatile("cp.async.wait_group 1;\n");
        else               asm volatile("cp.async.wait_group 0;\n");
        __syncthreads();
        compute(t % STG);
        if (t + 2 < ntile) issue(t + 2, (t + 2) % STG);
    }

    const int g = lane >> 2, q = lane & 3;

    if (FSTAT) {
        // fp16 C store (all rows incl. padding) + masked BN stats from fp32 accs.
        float sum[8], sq[8];
        #pragma unroll
        for (int i = 0; i < 8; ++i) { sum[i] = 0.f; sq[i] = 0.f; }
        #pragma unroll
        for (int mt = 0; mt < MT; ++mt) {
            int rr = wm*64 + mt*16 + g;
            bool ok0 = (rr & 63) < K_;
            bool ok1 = ((rr + 8) & 63) < K_;
            #pragma unroll
            for (int nt = 0; nt < 4; ++nt) {
                int c = n0 + wn*32 + nt*8 + q*2;
                float b0 = bias[c], b1 = bias[c+1];
                float v00 = acc[mt][nt][0] + b0, v01 = acc[mt][nt][1] + b1;
                float v10 = acc[mt][nt][2] + b0, v11 = acc[mt][nt][3] + b1;
                int r = m0 + rr;
                *(__half2*)&Ch[(size_t)r*ldc + c]     = __floats2half2_rn(v00, v01);
                *(__half2*)&Ch[(size_t)(r+8)*ldc + c] = __floats2half2_rn(v10, v11);
                if (ok0) { sum[nt*2]   += v00; sq[nt*2]   += v00*v00;
                           sum[nt*2+1] += v01; sq[nt*2+1] += v01*v01; }
                if (ok1) { sum[nt*2]   += v10; sq[nt*2]   += v10*v10;
                           sum[nt*2+1] += v11; sq[nt*2+1] += v11*v11; }
            }
        }
        #pragma unroll
        for (int off = 4; off < 32; off <<= 1) {
            #pragma unroll
            for (int i = 0; i < 8; ++i) {
                sum[i] += __shfl_xor_sync(0xffffffffu, sum[i], off);
                sq[i]  += __shfl_xor_sync(0xffffffffu, sq[i],  off);
            }
        }
        if (lane < 4) {
            #pragma unroll
            for (int nt = 0; nt < 4; ++nt) {
                #pragma unroll
                for (int j = 0; j < 2; ++j) {
                    int c = n0 + wn*32 + nt*8 + lane*2 + j;
                    atomicAdd(&stats[c],      sum[nt*2+j]);
                    atomicAdd(&stats[H_ + c], sq[nt*2+j]);
                }
            }
        }
    } else {
        // 2 batches per CTA; warp wm owns batch 2*by+wm (its 64 rows).
        // Masked max over K, xor-shuffle across g-lanes, direct store.
        float mx[8];
        #pragma unroll
        for (int i = 0; i < 8; ++i) mx[i] = -3.4e38f;
        #pragma unroll
        for (int mt = 0; mt < MT; ++mt) {
            int k0 = mt*16 + g;               // row within batch
            bool ok0 = k0 < K_, ok1 = (k0 + 8) < K_;
            #pragma unroll
            for (int nt = 0; nt < 4; ++nt) {
                int c = n0 + wn*32 + nt*8 + q*2;
                float b0 = bias[c], b1 = bias[c+1];
                if (ok0) { mx[nt*2]   = fmaxf(mx[nt*2],   acc[mt][nt][0] + b0);
                           mx[nt*2+1] = fmaxf(mx[nt*2+1], acc[mt][nt][1] + b1); }
                if (ok1) { mx[nt*2]   = fmaxf(mx[nt*2],   acc[mt][nt][2] + b0);
                           mx[nt*2+1] = fmaxf(mx[nt*2+1], acc[mt][nt][3] + b1); }
            }
        }
        #pragma unroll
        for (int off = 4; off < 32; off <<= 1)
            #pragma unroll
            for (int i = 0; i < 8; ++i)
                mx[i] = fmaxf(mx[i], __shfl_xor_sync(0xffffffffu, mx[i], off));
        if (lane < 4) {
            int b = blockIdx.y*2 + wm;
            #pragma unroll
            for (int nt = 0; nt < 4; ++nt) {
                int c = n0 + wn*32 + nt*8 + lane*2;
                *(float2*)&omax[(size_t)b*E_ + c] = make_float2(mx[nt*2], mx[nt*2+1]);
            }
        }
    }
}

// ---------------- BN apply + ReLU + fp16 into X[:,512:] (real rows only) ------
__global__ void bnapply_kernel(const float* __restrict__ gamma, const float* __restrict__ beta)
{
    int i = blockIdx.x*256 + threadIdx.x;    // 0..M_*H_/2-1
    int row = i >> 8;                        // real row 0..14847
    int cp = (i & 255)*2;
    int b = row / K_;
    int k = row - b*K_;
    size_t r = (size_t)(b*64 + k);
    __half2 x2 = *(const __half2*)&g_hpre[r*H_ + cp];
    const float invM = 1.f / (float)M_;
    float y0, y1;
    {
        float mu  = g_stats[cp] * invM;
        float var = g_stats[H_ + cp] * invM - mu*mu;
        y0 = fmaxf((__low2float(x2) - mu) * rsqrtf(var + 1e-5f) * gamma[cp] + beta[cp], 0.f);
    }
    {
        float mu  = g_stats[cp+1] * invM;
        float var = g_stats[H_ + cp+1] * invM - mu*mu;
        y1 = fmaxf((__high2float(x2) - mu) * rsqrtf(var + 1e-5f) * gamma[cp+1] + beta[cp+1], 0.f);
    }
    *(__half2*)&g_X[r*1024 + 512 + cp] = __floats2half2_rn(y0, y1);
}

// ---------------- launch ------------------------------------------------------
extern "C" void kernel_launch(void* const* d_in, const int* in_sizes, int n_in,
                              void* d_out, int out_size)
{
    const float* emb   = (const float*)d_in[0];
    const float* am    = (const float*)d_in[1];
    const float* Wfc   = (const float*)d_in[2];
    const float* bfc   = (const float*)d_in[3];
    const float* W1    = (const float*)d_in[4];
    const float* b1    = (const float*)d_in[5];
    const float* gamma = (const float*)d_in[6];
    const float* beta  = (const float*)d_in[7];
    const float* W2    = (const float*)d_in[8];
    const float* b2    = (const float*)d_in[9];
    float* out = (float*)d_out;

    void *pX, *pW1h, *pWcat, *pH, *pB2, *pSt;
    cudaGetSymbolAddress(&pX,    g_X);
    cudaGetSymbolAddress(&pW1h,  g_W1h);
    cudaGetSymbolAddress(&pWcat, g_Wcat);
    cudaGetSymbolAddress(&pH,    g_hpre);
    cudaGetSymbolAddress(&pB2,   g_bias2);
    cudaGetSymbolAddress(&pSt,   g_stats);

    prep_kernel<<<4096, 256>>>(Wfc, bfc, W1, W2, b2);
    topk_kernel<<<B_, N_>>>(am);
    gather_kernel<<<M_, 128>>>(emb);
    // GEMM1: hpre(fp16) = base @ W1^T + b1, fused BN stats (masked, fp32 accs)
    gemm_tc<true><<<dim3(H_/BN, MP_/BMt), 256>>>(
        (const __half*)pX, 1024, (const __half*)pW1h, D_,
        (__half*)pH, H_, b1, D_, (float*)pSt, nullptr);
    bnapply_kernel<<<(M_*H_/2)/256, 256>>>(gamma, beta);
    // GEMM2: out[b,:] = max_k( X @ [Wfc|W2]^T + (b_fc+b2) ), warp-local max epilogue
    gemm_tc<false><<<dim3(E_/BN, MP_/BMt), 256>>>(
        (const __half*)pX, 1024, (const __half*)pWcat, 1024,
        nullptr, 0, (const float*)pB2, 1024, nullptr, out);
}

// round 6
// speedup vs baseline: 1.1725x; 1.0163x over previous
#include <cuda_runtime.h>
#include <cuda_fp16.h>
#include <cstdint>

#define B_ 256
#define N_ 192
#define D_ 512
#define E_ 1024
#define H_ 512
#define K_ 58
#define M_ (B_*K_)        // 14848 real rows
#define MP_ (B_*64)       // 16384 padded rows (64 per batch, rows k>=58 stay zero)

// ---------------- scratch (static device globals; zero-init, no allocation) --
__device__ __half g_X[(size_t)MP_*1024];    // [MP,1024]: 0:512 base, 512:1024 bn(relu(h)); pad rows 0
__device__ __half g_hpre[(size_t)MP_*H_];   // [MP,512] fp16 pre-BN hidden
__device__ __half g_W1h[H_*D_];             // fp16 W1
__device__ __half g_Wcat[E_*1024];          // fp16 [W_fc | W2]
__device__ float  g_bias2[E_];              // b_fc + b2
__device__ float  g_stats[2*H_];            // col sums / sumsq
__device__ int    g_idx[B_*K_];             // selected patch indices

// ---------------- prep ---------------------------------------------------------
__global__ void prep_kernel(const float* __restrict__ Wfc, const float* __restrict__ bfc,
                            const float* __restrict__ W1,  const float* __restrict__ W2,
                            const float* __restrict__ b2)
{
    int i = blockIdx.x*blockDim.x + threadIdx.x;   // 0..1048575
    {
        int e = i >> 10, c = i & 1023;
        float v = (c < 512) ? Wfc[e*512 + c] : W2[e*512 + (c - 512)];
        g_Wcat[i] = __float2half_rn(v);
    }
    if (i < H_*D_) g_W1h[i] = __float2half_rn(W1[i]);
    if (i < E_)    g_bias2[i] = bfc[i] + b2[i];
    if (i < 2*H_)  g_stats[i] = 0.f;
}

// ---------------- top-K by rank counting (exact lax.top_k set semantics) -----
__global__ void topk_kernel(const float* __restrict__ am)
{
    __shared__ float sv[N_];
    __shared__ int cnt;
    int b = blockIdx.x, t = threadIdx.x;
    if (t == 0) cnt = 0;
    sv[t] = am[(size_t)b*((N_+1)*(N_+1)) + 1 + t];
    __syncthreads();
    float my = sv[t];
    int r = 0;
    #pragma unroll 8
    for (int i = 0; i < N_; ++i) {
        float v = sv[i];
        r += (v > my) || (v == my && i < t);
    }
    if (r < K_) {
        int p = atomicAdd(&cnt, 1);
        g_idx[b*K_ + p] = t;
    }
}

// ---------------- gather + L2 normalize + fp16 (into padded layout) -----------
__global__ void gather_kernel(const float* __restrict__ emb)
{
    int row = blockIdx.x;                 // 0..M_-1
    int b   = row / K_;
    int k   = row - b*K_;
    int p   = g_idx[row];
    const float4* src = (const float4*)(emb + (size_t)(b*N_ + p)*D_);
    int t = threadIdx.x;
    float4 v = src[t];
    float s = v.x*v.x + v.y*v.y + v.z*v.z + v.w*v.w;
    #pragma unroll
    for (int o = 16; o; o >>= 1) s += __shfl_xor_sync(0xffffffffu, s, o);
    __shared__ float sm[4];
    if ((t & 31) == 0) sm[t >> 5] = s;
    __syncthreads();
    float nrm = sqrtf(sm[0] + sm[1] + sm[2] + sm[3]) + 1e-8f;
    size_t r = (size_t)(b*64 + k);
    __half2* dst = (__half2*)(g_X + r*1024 + t*4);
    dst[0] = __floats2half2_rn(v.x/nrm, v.y/nrm);
    dst[1] = __floats2half2_rn(v.z/nrm, v.w/nrm);
}

// ---------------- fp16 tensor-core GEMM: C = A @ B^T + bias -------------------
// BM=256, BN=128, BK=64, 512 threads (16 warps, 4x4; warp tile 64x32).
// 3-stage cp.async ring (dynamic smem 144KB), SW128-style swizzle, ldmatrix.
// FSTAT: fp16 C store + masked BN column sums/sumsq.
// !FSTAT: BM=256 = 4 padded batches; warp-local masked max over K -> omax.
#define BMt 256
#define BN 128
#define BK 64
#define STG 3
#define STAGE_BYTES ((BMt + BN)*BK*2)     // 49152
#define A_BYTES (BMt*BK*2)                // 32768

__device__ __forceinline__ void cp16(uint32_t dst, const void* src) {
    asm volatile("cp.async.cg.shared.global [%0], [%1], 16;\n" :: "r"(dst), "l"(src));
}
__device__ __forceinline__ uint32_t smem_u32(const void* p) {
    uint32_t a;
    asm("{ .reg .u64 t; cvta.to.shared.u64 t, %1; cvt.u32.u64 %0, t; }" : "=r"(a) : "l"(p));
    return a;
}

template<bool FSTAT>
__global__ __launch_bounds__(512, 1)
void gemm_tc(const __half* __restrict__ A, int lda,
             const __half* __restrict__ Bm, int ldb,
             __half* __restrict__ Ch, int ldc,
             const float* __restrict__ bias, int Kdim,
             float* __restrict__ stats, float* __restrict__ omax)
{
    extern __shared__ __half sh[];
    const int tid  = threadIdx.x;
    const int lane = tid & 31, wid = tid >> 5;
    const int wm = wid >> 2, wn = wid & 3;        // 4x4 warp grid
    const int m0 = blockIdx.y*BMt, n0 = blockIdx.x*BN;

    uint32_t sbase = smem_u32(sh);

    float acc[4][4][4];
    #pragma unroll
    for (int i = 0; i < 4; ++i)
        #pragma unroll
        for (int j = 0; j < 4; ++j)
            #pragma unroll
            for (int k = 0; k < 4; ++k) acc[i][j][k] = 0.f;

    // global->smem descriptors: rows of 64 halfs = 8 x 16B chunks, XOR-8 swizzle
    const int cr = tid >> 3;          // 0..63
    const int cc = tid & 7;           // chunk col
    const __half* Ag[4]; uint32_t oA[4];
    #pragma unroll
    for (int i = 0; i < 4; ++i) {
        int r = cr + i*64;
        Ag[i] = A + (size_t)(m0 + r)*lda + cc*8;
        oA[i] = r*128 + ((cc ^ (r & 7))*16);
    }
    const __half* Bg[2]; uint32_t oB[2];
    #pragma unroll
    for (int i = 0; i < 2; ++i) {
        int r = cr + i*64;
        Bg[i] = Bm + (size_t)(n0 + r)*ldb + cc*8;
        oB[i] = A_BYTES + r*128 + ((cc ^ (r & 7))*16);
    }

    // ldmatrix per-lane descriptors
    const int mi  = lane >> 3;
    const int lr8 = lane & 7;
    int arow[4];
    #pragma unroll
    for (int mt = 0; mt < 4; ++mt) arow[mt] = wm*64 + mt*16 + ((mi & 1) << 3) + lr8;
    const int akadd = mi >> 1;
    int brow[2];
    #pragma unroll
    for (int p = 0; p < 2; ++p) brow[p] = wn*32 + ((2*p + (mi >> 1)) << 3) + lr8;
    const int bkadd = mi & 1;

    auto issue = [&](int kt, int st) {
        uint32_t so = sbase + st*STAGE_BYTES;
        int ko = kt*BK;
        #pragma unroll
        for (int i = 0; i < 4; ++i) cp16(so + oA[i], Ag[i] + ko);
        #pragma unroll
        for (int i = 0; i < 2; ++i) cp16(so + oB[i], Bg[i] + ko);
        asm volatile("cp.async.commit_group;\n");
    };

    auto compute = [&](int st) {
        uint32_t abase = sbase + st*STAGE_BYTES;
        uint32_t bbase = abase + A_BYTES;
        #pragma unroll
        for (int ks = 0; ks < 4; ++ks) {
            uint32_t a[4][4], bb[4][2];
            #pragma unroll
            for (int mt = 0; mt < 4; ++mt) {
                uint32_t ad = abase + arow[mt]*128 + (((2*ks + akadd) ^ lr8)*16);
                asm volatile("ldmatrix.sync.aligned.m8n8.x4.shared.b16 {%0,%1,%2,%3},[%4];"
                    : "=r"(a[mt][0]), "=r"(a[mt][1]), "=r"(a[mt][2]), "=r"(a[mt][3]) : "r"(ad));
            }
            #pragma unroll
            for (int p = 0; p < 2; ++p) {
                uint32_t bd = bbase + brow[p]*128 + (((2*ks + bkadd) ^ lr8)*16);
                asm volatile("ldmatrix.sync.aligned.m8n8.x4.shared.b16 {%0,%1,%2,%3},[%4];"
                    : "=r"(bb[2*p][0]), "=r"(bb[2*p][1]),
                      "=r"(bb[2*p+1][0]), "=r"(bb[2*p+1][1]) : "r"(bd));
            }
            #pragma unroll
            for (int mt = 0; mt < 4; ++mt)
                #pragma unroll
                for (int nt = 0; nt < 4; ++nt)
                    asm volatile(
                        "mma.sync.aligned.m16n8k16.row.col.f32.f16.f16.f32 "
                        "{%0,%1,%2,%3},{%4,%5,%6,%7},{%8,%9},{%0,%1,%2,%3};\n"
                        : "+f"(acc[mt][nt][0]), "+f"(acc[mt][nt][1]),
                          "+f"(acc[mt][nt][2]), "+f"(acc[mt][nt][3])
                        : "r"(a[mt][0]), "r"(a[mt][1]), "r"(a[mt][2]), "r"(a[mt][3]),
                          "r"(bb[nt][0]), "r"(bb[nt][1]));
        }
    };

    const int ntile = Kdim / BK;
    issue(0, 0);
    issue(1, 1);
    for (int t = 0; t < ntile; ++t) {
        if (t + 1 < ntile) asm volatile("cp.async.wait_group 1;\n" ::: "memory");
        else               asm volatile("cp.async.wait_group 0;\n" ::: "memory");
        __syncthreads();
        compute(t % STG);
        if (t + 2 < ntile) issue(t + 2, (t + 2) % STG);
    }

    const int g = lane >> 2, q = lane & 3;

    if (FSTAT) {
        // fp16 C store (all rows incl. padding) + masked BN stats from fp32 accs.
        float sum[8], sq[8];
        #pragma unroll
        for (int i = 0; i < 8; ++i) { sum[i] = 0.f; sq[i] = 0.f; }
        #pragma unroll
        for (int mt = 0; mt < 4; ++mt) {
            int rr = wm*64 + mt*16 + g;
            bool ok0 = (rr & 63) < K_;
            bool ok1 = ((rr + 8) & 63) < K_;
            #pragma unroll
            for (int nt = 0; nt < 4; ++nt) {
                int c = n0 + wn*32 + nt*8 + q*2;
                float b0 = bias[c], b1 = bias[c+1];
                float v00 = acc[mt][nt][0] + b0, v01 = acc[mt][nt][1] + b1;
                float v10 = acc[mt][nt][2] + b0, v11 = acc[mt][nt][3] + b1;
                int r = m0 + rr;
                *(__half2*)&Ch[(size_t)r*ldc + c]     = __floats2half2_rn(v00, v01);
                *(__half2*)&Ch[(size_t)(r+8)*ldc + c] = __floats2half2_rn(v10, v11);
                if (ok0) { sum[nt*2]   += v00; sq[nt*2]   += v00*v00;
                           sum[nt*2+1] += v01; sq[nt*2+1] += v01*v01; }
                if (ok1) { sum[nt*2]   += v10; sq[nt*2]   += v10*v10;
                           sum[nt*2+1] += v11; sq[nt*2+1] += v11*v11; }
            }
        }
        #pragma unroll
        for (int off = 4; off < 32; off <<= 1) {
            #pragma unroll
            for (int i = 0; i < 8; ++i) {
                sum[i] += __shfl_xor_sync(0xffffffffu, sum[i], off);
                sq[i]  += __shfl_xor_sync(0xffffffffu, sq[i],  off);
            }
        }
        if (lane < 4) {
            #pragma unroll
            for (int nt = 0; nt < 4; ++nt) {
                #pragma unroll
                for (int j = 0; j < 2; ++j) {
                    int c = n0 + wn*32 + nt*8 + lane*2 + j;
                    atomicAdd(&stats[c],      sum[nt*2+j]);
                    atomicAdd(&stats[H_ + c], sq[nt*2+j]);
                }
            }
        }
    } else {
        // 4 batches per CTA; warp wm owns batch 4*by+wm (rows wm*64..wm*64+63).
        float mx[8];
        #pragma unroll
        for (int i = 0; i < 8; ++i) mx[i] = -3.4e38f;
        #pragma unroll
        for (int mt = 0; mt < 4; ++mt) {
            int k0 = mt*16 + g;               // row within batch
            bool ok0 = k0 < K_, ok1 = (k0 + 8) < K_;
            #pragma unroll
            for (int nt = 0; nt < 4; ++nt) {
                int c = n0 + wn*32 + nt*8 + q*2;
                float b0 = bias[c], b1 = bias[c+1];
                if (ok0) { mx[nt*2]   = fmaxf(mx[nt*2],   acc[mt][nt][0] + b0);
                           mx[nt*2+1] = fmaxf(mx[nt*2+1], acc[mt][nt][1] + b1); }
                if (ok1) { mx[nt*2]   = fmaxf(mx[nt*2],   acc[mt][nt][2] + b0);
                           mx[nt*2+1] = fmaxf(mx[nt*2+1], acc[mt][nt][3] + b1); }
            }
        }
        #pragma unroll
        for (int off = 4; off < 32; off <<= 1)
            #pragma unroll
            for (int i = 0; i < 8; ++i)
                mx[i] = fmaxf(mx[i], __shfl_xor_sync(0xffffffffu, mx[i], off));
        if (lane < 4) {
            int b = blockIdx.y*4 + wm;
            #pragma unroll
            for (int nt = 0; nt < 4; ++nt) {
                int c = n0 + wn*32 + nt*8 + lane*2;
                *(float2*)&omax[(size_t)b*E_ + c] = make_float2(mx[nt*2], mx[nt*2+1]);
            }
        }
    }
}

// ---------------- BN apply + ReLU + fp16 into X[:,512:] (real rows only) ------
__global__ void bnapply_kernel(const float* __restrict__ gamma, const float* __restrict__ beta)
{
    int i = blockIdx.x*256 + threadIdx.x;    // 0..M_*H_/2-1
    int row = i >> 8;                        // real row 0..14847
    int cp = (i & 255)*2;
    int b = row / K_;
    int k = row - b*K_;
    size_t r = (size_t)(b*64 + k);
    __half2 x2 = *(const __half2*)&g_hpre[r*H_ + cp];
    const float invM = 1.f / (float)M_;
    float y0, y1;
    {
        float mu  = g_stats[cp] * invM;
        float var = g_stats[H_ + cp] * invM - mu*mu;
        y0 = fmaxf((__low2float(x2) - mu) * rsqrtf(var + 1e-5f) * gamma[cp] + beta[cp], 0.f);
    }
    {
        float mu  = g_stats[cp+1] * invM;
        float var = g_stats[H_ + cp+1] * invM - mu*mu;
        y1 = fmaxf((__high2float(x2) - mu) * rsqrtf(var + 1e-5f) * gamma[cp+1] + beta[cp+1], 0.f);
    }
    *(__half2*)&g_X[r*1024 + 512 + cp] = __floats2half2_rn(y0, y1);
}

// ---------------- launch ------------------------------------------------------
extern "C" void kernel_launch(void* const* d_in, const int* in_sizes, int n_in,
                              void* d_out, int out_size)
{
    const float* emb   = (const float*)d_in[0];
    const float* am    = (const float*)d_in[1];
    const float* Wfc   = (const float*)d_in[2];
    const float* bfc   = (const float*)d_in[3];
    const float* W1    = (const float*)d_in[4];
    const float* b1    = (const float*)d_in[5];
    const float* gamma = (const float*)d_in[6];
    const float* beta  = (const float*)d_in[7];
    const float* W2    = (const float*)d_in[8];
    const float* b2    = (const float*)d_in[9];
    float* out = (float*)d_out;

    void *pX, *pW1h, *pWcat, *pH, *pB2, *pSt;
    cudaGetSymbolAddress(&pX,    g_X);
    cudaGetSymbolAddress(&pW1h,  g_W1h);
    cudaGetSymbolAddress(&pWcat, g_Wcat);
    cudaGetSymbolAddress(&pH,    g_hpre);
    cudaGetSymbolAddress(&pB2,   g_bias2);
    cudaGetSymbolAddress(&pSt,   g_stats);

    const int SMEM = STG*STAGE_BYTES;   // 147456
    cudaFuncSetAttribute(gemm_tc<true>,  cudaFuncAttributeMaxDynamicSharedMemorySize, SMEM);
    cudaFuncSetAttribute(gemm_tc<false>, cudaFuncAttributeMaxDynamicSharedMemorySize, SMEM);

    prep_kernel<<<4096, 256>>>(Wfc, bfc, W1, W2, b2);
    topk_kernel<<<B_, N_>>>(am);
    gather_kernel<<<M_, 128>>>(emb);
    // GEMM1: hpre(fp16) = base @ W1^T + b1, fused BN stats (K=512 -> 8 tiles)
    gemm_tc<true><<<dim3(H_/BN, MP_/BMt), 512, SMEM>>>(
        (const __half*)pX, 1024, (const __half*)pW1h, D_,
        (__half*)pH, H_, b1, D_, (float*)pSt, nullptr);
    bnapply_kernel<<<(M_*H_/2)/256, 256>>>(gamma, beta);
    // GEMM2: out[b,:] = max_k( X @ [Wfc|W2]^T + (b_fc+b2) ), warp-local max epilogue
    gemm_tc<false><<<dim3(E_/BN, MP_/BMt), 512, SMEM>>>(
        (const __half*)pX, 1024, (const __half*)pWcat, 1024,
        nullptr, 0, (const float*)pB2, 1024, nullptr, out);
}

// round 7
// speedup vs baseline: 1.3017x; 1.1101x over previous
#include <cuda_runtime.h>
#include <cuda_fp16.h>
#include <cstdint>

#define B_ 256
#define N_ 192
#define D_ 512
#define E_ 1024
#define H_ 512
#define K_ 58
#define M_ (B_*K_)        // 14848 real rows
#define MP_ (B_*64)       // 16384 padded rows (64 per batch, rows k>=58 stay zero)

// ---------------- scratch (static device globals; zero-init, no allocation) --
__device__ __half g_X[(size_t)MP_*1024];    // [MP,1024]: 0:512 base, 512:1024 bn(relu(h)); pad rows 0
__device__ __half g_hpre[(size_t)MP_*H_];   // [MP,512] fp16 pre-BN hidden
__device__ __half g_W1h[H_*D_];             // fp16 W1
__device__ __half g_Wcat[E_*1024];          // fp16 [W_fc | W2]
__device__ float  g_bias2[E_];              // b_fc + b2
__device__ float  g_stats[2*H_];            // col sums / sumsq
__device__ int    g_idx[B_*K_];             // selected patch indices

// ---------------- prep ---------------------------------------------------------
__global__ void prep_kernel(const float* __restrict__ Wfc, const float* __restrict__ bfc,
                            const float* __restrict__ W1,  const float* __restrict__ W2,
                            const float* __restrict__ b2)
{
    int i = blockIdx.x*blockDim.x + threadIdx.x;   // 0..1048575
    {
        int e = i >> 10, c = i & 1023;
        float v = (c < 512) ? Wfc[e*512 + c] : W2[e*512 + (c - 512)];
        g_Wcat[i] = __float2half_rn(v);
    }
    if (i < H_*D_) g_W1h[i] = __float2half_rn(W1[i]);
    if (i < E_)    g_bias2[i] = bfc[i] + b2[i];
    if (i < 2*H_)  g_stats[i] = 0.f;
}

// ---------------- top-K by rank counting (exact lax.top_k set semantics) -----
__global__ void topk_kernel(const float* __restrict__ am)
{
    __shared__ float sv[N_];
    __shared__ int cnt;
    int b = blockIdx.x, t = threadIdx.x;
    if (t == 0) cnt = 0;
    sv[t] = am[(size_t)b*((N_+1)*(N_+1)) + 1 + t];
    __syncthreads();
    float my = sv[t];
    int r = 0;
    #pragma unroll 8
    for (int i = 0; i < N_; ++i) {
        float v = sv[i];
        r += (v > my) || (v == my && i < t);
    }
    if (r < K_) {
        int p = atomicAdd(&cnt, 1);
        g_idx[b*K_ + p] = t;
    }
}

// ---------------- gather + L2 normalize + fp16 (into padded layout) -----------
__global__ void gather_kernel(const float* __restrict__ emb)
{
    int row = blockIdx.x;                 // 0..M_-1
    int b   = row / K_;
    int k   = row - b*K_;
    int p   = g_idx[row];
    const float4* src = (const float4*)(emb + (size_t)(b*N_ + p)*D_);
    int t = threadIdx.x;
    float4 v = src[t];
    float s = v.x*v.x + v.y*v.y + v.z*v.z + v.w*v.w;
    #pragma unroll
    for (int o = 16; o; o >>= 1) s += __shfl_xor_sync(0xffffffffu, s, o);
    __shared__ float sm[4];
    if ((t & 31) == 0) sm[t >> 5] = s;
    __syncthreads();
    float nrm = sqrtf(sm[0] + sm[1] + sm[2] + sm[3]) + 1e-8f;
    size_t r = (size_t)(b*64 + k);
    __half2* dst = (__half2*)(g_X + r*1024 + t*4);
    dst[0] = __floats2half2_rn(v.x/nrm, v.y/nrm);
    dst[1] = __floats2half2_rn(v.z/nrm, v.w/nrm);
}

// ---------------- fp16 tensor-core GEMM: C = A @ B^T + bias -------------------
// BM=128, BN=128, BK=64; 128 threads = 4 warps (2x2), warp tile 64x64.
// 3-stage cp.async ring (96KB dynamic smem) -> 2 CTAs/SM.
// mma:ldsm = 32:8 per warp-k16 (double reuse vs 64x32 tiles).
// FSTAT: fp16 C store + masked BN column sums/sumsq.
// !FSTAT: BM=128 = 2 padded batches; warp-local masked max over K -> omax.
#define BMt 128
#define BN 128
#define BK 64
#define STG 3
#define STAGE_BYTES ((BMt + BN)*BK*2)     // 32768
#define A_BYTES (BMt*BK*2)                // 16384

__device__ __forceinline__ void cp16(uint32_t dst, const void* src) {
    asm volatile("cp.async.cg.shared.global [%0], [%1], 16;\n" :: "r"(dst), "l"(src));
}
__device__ __forceinline__ uint32_t smem_u32(const void* p) {
    uint32_t a;
    asm("{ .reg .u64 t; cvta.to.shared.u64 t, %1; cvt.u32.u64 %0, t; }" : "=r"(a) : "l"(p));
    return a;
}

template<bool FSTAT>
__global__ __launch_bounds__(128)
void gemm_tc(const __half* __restrict__ A, int lda,
             const __half* __restrict__ Bm, int ldb,
             __half* __restrict__ Ch, int ldc,
             const float* __restrict__ bias, int Kdim,
             float* __restrict__ stats, float* __restrict__ omax)
{
    extern __shared__ __half sh[];
    const int tid  = threadIdx.x;
    const int lane = tid & 31, wid = tid >> 5;
    const int wm = wid >> 1, wn = wid & 1;        // 2x2 warp grid, tile 64x64
    const int m0 = blockIdx.y*BMt, n0 = blockIdx.x*BN;

    uint32_t sbase = smem_u32(sh);

    float acc[4][8][4];
    #pragma unroll
    for (int i = 0; i < 4; ++i)
        #pragma unroll
        for (int j = 0; j < 8; ++j)
            #pragma unroll
            for (int k = 0; k < 4; ++k) acc[i][j][k] = 0.f;

    // global->smem: 256 rows x 8 chunks(16B) = 2048 chunks / 128 thr = 16 each
    const int cr = tid >> 3;          // 0..15
    const int cc = tid & 7;           // chunk col
    const __half* Ag[8]; uint32_t oA[8];
    #pragma unroll
    for (int i = 0; i < 8; ++i) {
        int r = cr + i*16;
        Ag[i] = A + (size_t)(m0 + r)*lda + cc*8;
        oA[i] = r*128 + ((cc ^ (r & 7))*16);
    }
    const __half* Bg[8]; uint32_t oB[8];
    #pragma unroll
    for (int i = 0; i < 8; ++i) {
        int r = cr + i*16;
        Bg[i] = Bm + (size_t)(n0 + r)*ldb + cc*8;
        oB[i] = A_BYTES + r*128 + ((cc ^ (r & 7))*16);
    }

    // ldmatrix per-lane descriptors
    const int mi  = lane >> 3;
    const int lr8 = lane & 7;
    int arow[4];
    #pragma unroll
    for (int mt = 0; mt < 4; ++mt) arow[mt] = wm*64 + mt*16 + ((mi & 1) << 3) + lr8;
    const int akadd = mi >> 1;
    int brow[4];
    #pragma unroll
    for (int p = 0; p < 4; ++p) brow[p] = wn*64 + ((2*p + (mi >> 1)) << 3) + lr8;
    const int bkadd = mi & 1;

    auto issue = [&](int kt, int st) {
        uint32_t so = sbase + st*STAGE_BYTES;
        int ko = kt*BK;
        #pragma unroll
        for (int i = 0; i < 8; ++i) cp16(so + oA[i], Ag[i] + ko);
        #pragma unroll
        for (int i = 0; i < 8; ++i) cp16(so + oB[i], Bg[i] + ko);
        asm volatile("cp.async.commit_group;\n");
    };

    auto compute = [&](int st) {
        uint32_t abase = sbase + st*STAGE_BYTES;
        uint32_t bbase = abase + A_BYTES;
        #pragma unroll
        for (int ks = 0; ks < 4; ++ks) {
            uint32_t a[4][4], bb[8][2];
            #pragma unroll
            for (int mt = 0; mt < 4; ++mt) {
                uint32_t ad = abase + arow[mt]*128 + (((2*ks + akadd) ^ lr8)*16);
                asm volatile("ldmatrix.sync.aligned.m8n8.x4.shared.b16 {%0,%1,%2,%3},[%4];"
                    : "=r"(a[mt][0]), "=r"(a[mt][1]), "=r"(a[mt][2]), "=r"(a[mt][3]) : "r"(ad));
            }
            #pragma unroll
            for (int p = 0; p < 4; ++p) {
                uint32_t bd = bbase + brow[p]*128 + (((2*ks + bkadd) ^ lr8)*16);
                asm volatile("ldmatrix.sync.aligned.m8n8.x4.shared.b16 {%0,%1,%2,%3},[%4];"
                    : "=r"(bb[2*p][0]), "=r"(bb[2*p][1]),
                      "=r"(bb[2*p+1][0]), "=r"(bb[2*p+1][1]) : "r"(bd));
            }
            #pragma unroll
            for (int mt = 0; mt < 4; ++mt)
                #pragma unroll
                for (int nt = 0; nt < 8; ++nt)
                    asm volatile(
                        "mma.sync.aligned.m16n8k16.row.col.f32.f16.f16.f32 "
                        "{%0,%1,%2,%3},{%4,%5,%6,%7},{%8,%9},{%0,%1,%2,%3};\n"
                        : "+f"(acc[mt][nt][0]), "+f"(acc[mt][nt][1]),
                          "+f"(acc[mt][nt][2]), "+f"(acc[mt][nt][3])
                        : "r"(a[mt][0]), "r"(a[mt][1]), "r"(a[mt][2]), "r"(a[mt][3]),
                          "r"(bb[nt][0]), "r"(bb[nt][1]));
        }
    };

    const int ntile = Kdim / BK;
    issue(0, 0);
    issue(1, 1);
    for (int t = 0; t < ntile; ++t) {
        if (t + 1 < ntile) asm volatile("cp.async.wait_group 1;\n" ::: "memory");
        else               asm volatile("cp.async.wait_group 0;\n" ::: "memory");
        __syncthreads();
        compute(t % STG);
        if (t + 2 < ntile) issue(t + 2, (t + 2) % STG);
    }

    const int g = lane >> 2, q = lane & 3;

    if (FSTAT) {
        // fp16 C store (all rows incl. padding) + masked BN stats from fp32 accs.
        float sum[16], sq[16];
        #pragma unroll
        for (int i = 0; i < 16; ++i) { sum[i] = 0.f; sq[i] = 0.f; }
        #pragma unroll
        for (int mt = 0; mt < 4; ++mt) {
            int rr = wm*64 + mt*16 + g;
            bool ok0 = (rr & 63) < K_;
            bool ok1 = ((rr + 8) & 63) < K_;
            #pragma unroll
            for (int nt = 0; nt < 8; ++nt) {
                int c = n0 + wn*64 + nt*8 + q*2;
                float b0 = bias[c], b1 = bias[c+1];
                float v00 = acc[mt][nt][0] + b0, v01 = acc[mt][nt][1] + b1;
                float v10 = acc[mt][nt][2] + b0, v11 = acc[mt][nt][3] + b1;
                int r = m0 + rr;
                *(__half2*)&Ch[(size_t)r*ldc + c]     = __floats2half2_rn(v00, v01);
                *(__half2*)&Ch[(size_t)(r+8)*ldc + c] = __floats2half2_rn(v10, v11);
                if (ok0) { sum[nt*2]   += v00; sq[nt*2]   += v00*v00;
                           sum[nt*2+1] += v01; sq[nt*2+1] += v01*v01; }
                if (ok1) { sum[nt*2]   += v10; sq[nt*2]   += v10*v10;
                           sum[nt*2+1] += v11; sq[nt*2+1] += v11*v11; }
            }
        }
        #pragma unroll
        for (int off = 4; off < 32; off <<= 1) {
            #pragma unroll
            for (int i = 0; i < 16; ++i) {
                sum[i] += __shfl_xor_sync(0xffffffffu, sum[i], off);
                sq[i]  += __shfl_xor_sync(0xffffffffu, sq[i],  off);
            }
        }
        if (lane < 4) {
            #pragma unroll
            for (int nt = 0; nt < 8; ++nt) {
                #pragma unroll
                for (int j = 0; j < 2; ++j) {
                    int c = n0 + wn*64 + nt*8 + lane*2 + j;
                    atomicAdd(&stats[c],      sum[nt*2+j]);
                    atomicAdd(&stats[H_ + c], sq[nt*2+j]);
                }
            }
        }
    } else {
        // 2 batches per CTA; warp row wm owns batch 2*by+wm (rows wm*64..+63).
        float mx[16];
        #pragma unroll
        for (int i = 0; i < 16; ++i) mx[i] = -3.4e38f;
        #pragma unroll
        for (int mt = 0; mt < 4; ++mt) {
            int k0 = mt*16 + g;               // row within batch
            bool ok0 = k0 < K_, ok1 = (k0 + 8) < K_;
            #pragma unroll
            for (int nt = 0; nt < 8; ++nt) {
                int c = n0 + wn*64 + nt*8 + q*2;
                float b0 = bias[c], b1 = bias[c+1];
                if (ok0) { mx[nt*2]   = fmaxf(mx[nt*2],   acc[mt][nt][0] + b0);
                           mx[nt*2+1] = fmaxf(mx[nt*2+1], acc[mt][nt][1] + b1); }
                if (ok1) { mx[nt*2]   = fmaxf(mx[nt*2],   acc[mt][nt][2] + b0);
                           mx[nt*2+1] = fmaxf(mx[nt*2+1], acc[mt][nt][3] + b1); }
            }
        }
        #pragma unroll
        for (int off = 4; off < 32; off <<= 1)
            #pragma unroll
            for (int i = 0; i < 16; ++i)
                mx[i] = fmaxf(mx[i], __shfl_xor_sync(0xffffffffu, mx[i], off));
        if (lane < 4) {
            int b = blockIdx.y*2 + wm;
            #pragma unroll
            for (int nt = 0; nt < 8; ++nt) {
                int c = n0 + wn*64 + nt*8 + lane*2;
                *(float2*)&omax[(size_t)b*E_ + c] = make_float2(mx[nt*2], mx[nt*2+1]);
            }
        }
    }
}

// ---------------- BN apply + ReLU + fp16 into X[:,512:] (real rows only) ------
__global__ void bnapply_kernel(const float* __restrict__ gamma, const float* __restrict__ beta)
{
    int i = blockIdx.x*256 + threadIdx.x;    // 0..M_*H_/2-1
    int row = i >> 8;                        // real row 0..14847
    int cp = (i & 255)*2;
    int b = row / K_;
    int k = row - b*K_;
    size_t r = (size_t)(b*64 + k);
    __half2 x2 = *(const __half2*)&g_hpre[r*H_ + cp];
    const float invM = 1.f / (float)M_;
    float y0, y1;
    {
        float mu  = g_stats[cp] * invM;
        float var = g_stats[H_ + cp] * invM - mu*mu;
        y0 = fmaxf((__low2float(x2) - mu) * rsqrtf(var + 1e-5f) * gamma[cp] + beta[cp], 0.f);
    }
    {
        float mu  = g_stats[cp+1] * invM;
        float var = g_stats[H_ + cp+1] * invM - mu*mu;
        y1 = fmaxf((__high2float(x2) - mu) * rsqrtf(var + 1e-5f) * gamma[cp+1] + beta[cp+1], 0.f);
    }
    *(__half2*)&g_X[r*1024 + 512 + cp] = __floats2half2_rn(y0, y1);
}

// ---------------- launch ------------------------------------------------------
extern "C" void kernel_launch(void* const* d_in, const int* in_sizes, int n_in,
                              void* d_out, int out_size)
{
    const float* emb   = (const float*)d_in[0];
    const float* am    = (const float*)d_in[1];
    const float* Wfc   = (const float*)d_in[2];
    const float* bfc   = (const float*)d_in[3];
    const float* W1    = (const float*)d_in[4];
    const float* b1    = (const float*)d_in[5];
    const float* gamma = (const float*)d_in[6];
    const float* beta  = (const float*)d_in[7];
    const float* W2    = (const float*)d_in[8];
    const float* b2    = (const float*)d_in[9];
    float* out = (float*)d_out;

    void *pX, *pW1h, *pWcat, *pH, *pB2, *pSt;
    cudaGetSymbolAddress(&pX,    g_X);
    cudaGetSymbolAddress(&pW1h,  g_W1h);
    cudaGetSymbolAddress(&pWcat, g_Wcat);
    cudaGetSymbolAddress(&pH,    g_hpre);
    cudaGetSymbolAddress(&pB2,   g_bias2);
    cudaGetSymbolAddress(&pSt,   g_stats);

    const int SMEM = STG*STAGE_BYTES;   // 98304
    cudaFuncSetAttribute(gemm_tc<true>,  cudaFuncAttributeMaxDynamicSharedMemorySize, SMEM);
    cudaFuncSetAttribute(gemm_tc<false>, cudaFuncAttributeMaxDynamicSharedMemorySize, SMEM);

    prep_kernel<<<4096, 256>>>(Wfc, bfc, W1, W2, b2);
    topk_kernel<<<B_, N_>>>(am);
    gather_kernel<<<M_, 128>>>(emb);
    // GEMM1: hpre(fp16) = base @ W1^T + b1, fused BN stats (K=512 -> 8 tiles)
    gemm_tc<true><<<dim3(H_/BN, MP_/BMt), 128, SMEM>>>(
        (const __half*)pX, 1024, (const __half*)pW1h, D_,
        (__half*)pH, H_, b1, D_, (float*)pSt, nullptr);
    bnapply_kernel<<<(M_*H_/2)/256, 256>>>(gamma, beta);
    // GEMM2: out[b,:] = max_k( X @ [Wfc|W2]^T + (b_fc+b2) ), warp-local max epilogue
    gemm_tc<false><<<dim3(E_/BN, MP_/BMt), 128, SMEM>>>(
        (const __half*)pX, 1024, (const __half*)pWcat, 1024,
        nullptr, 0, (const float*)pB2, 1024, nullptr, out);
}